// round 9
// baseline (speedup 1.0000x reference)
#include <cuda_runtime.h>
#include <math.h>
#include <stdint.h>

// CGGRLoss fused, R9: bulk-async (TMA-path) smem pipeline.
// One block per row. Producer thread issues cp.async.bulk tiles 3 deep into a
// smem ring (mbarrier complete_tx); all 256 threads consume via LDS.128 with
// the lazily-rescaled online-softmax math. Last block finalizes (reductions,
// exact k-th largest radix select, masked-mean CE).

#define MAXN 8192
#define LOG2E 1.4426950408889634f
#define NST 3
#define TILE_BYTES 12288          // 768 float4 per tile = 3 per thread
#define TILE_F4 (TILE_BYTES / 16)

static __device__ float g_ce[MAXN];
static __device__ float g_conf[MAXN];
static __device__ float g_part[MAXN];     // ent_norm + 1 - margin
static __device__ unsigned g_key[MAXN];   // finalize scratch (radix keys)
static __device__ unsigned g_done;        // zero-init; reset in-kernel

__device__ __forceinline__ float ex2f(float x) {
    float y;
    asm("ex2.approx.ftz.f32 %0, %1;" : "=f"(y) : "f"(x));
    return y;   // ex2(-inf) = +0, ex2(0) = 1 exactly
}

__device__ __forceinline__ uint32_t smem_u32(const void* ptr) {
    uint32_t a;
    asm("{ .reg .u64 t; cvta.to.shared.u64 t, %1; cvt.u32.u64 %0, t; }"
        : "=r"(a) : "l"(ptr));
    return a;
}

#define MBAR_INIT(a, c) \
    asm volatile("mbarrier.init.shared.b64 [%0], %1;" :: "r"(a), "r"(c) : "memory")
#define MBAR_EXPECT_TX(a, b) \
    asm volatile("mbarrier.arrive.expect_tx.shared.b64 _, [%0], %1;" :: "r"(a), "r"(b) : "memory")
#define MBAR_ARRIVE(a) \
    asm volatile("mbarrier.arrive.shared.b64 _, [%0];" :: "r"(a) : "memory")

__device__ __forceinline__ void mbar_wait(uint32_t mbar, uint32_t parity) {
    asm volatile(
        "{\n\t"
        ".reg .pred P;\n\t"
        "WL_%=:\n\t"
        "mbarrier.try_wait.parity.acquire.cta.shared::cta.b64 P, [%0], %1, 0x989680;\n\t"
        "@P bra.uni WD_%=;\n\t"
        "bra.uni WL_%=;\n\t"
        "WD_%=:\n\t"
        "}"
        :: "r"(mbar), "r"(parity) : "memory");
}

__device__ __forceinline__ void mbar_wait_relaxed(uint32_t mbar, uint32_t parity) {
    asm volatile(
        "{\n\t"
        ".reg .pred P;\n\t"
        "WL_%=:\n\t"
        "mbarrier.try_wait.parity.relaxed.cta.shared::cta.b64 P, [%0], %1, 0x989680;\n\t"
        "@P bra.uni WD_%=;\n\t"
        "bra.uni WL_%=;\n\t"
        "WD_%=:\n\t"
        "}"
        :: "r"(mbar), "r"(parity) : "memory");
}

__device__ __forceinline__ void bulk_g2s(uint32_t dst_smem, const void* src_gmem,
                                         uint32_t bytes, uint32_t mbar) {
    asm volatile(
        "cp.async.bulk.shared::cta.global.mbarrier::complete_tx::bytes "
        "[%0], [%1], %2, [%3];"
        :: "r"(dst_smem), "l"(src_gmem), "r"(bytes), "r"(mbar) : "memory");
}

struct OS { float m1, m2, s, t; };

__device__ __forceinline__ void os_merge(OS& a, const OS& b) {
    float M1 = fmaxf(a.m1, b.m1);
    float M2 = fmaxf(fminf(a.m1, b.m1), fmaxf(a.m2, b.m2));
    float sa = (a.m1 == -INFINITY) ? 0.f : __expf(a.m1 - M1);
    float sb = (b.m1 == -INFINITY) ? 0.f : __expf(b.m1 - M1);
    a.s = a.s * sa + b.s * sb;
    a.t = a.t * sa + b.t * sb;
    a.m1 = M1; a.m2 = M2;
}

__device__ __forceinline__ float blk_max(float v, float* rbuf) {
    #pragma unroll
    for (int off = 16; off; off >>= 1)
        v = fmaxf(v, __shfl_xor_sync(0xffffffffu, v, off));
    if ((threadIdx.x & 31) == 0) rbuf[threadIdx.x >> 5] = v;
    __syncthreads();
    if (threadIdx.x < 8) {
        v = rbuf[threadIdx.x];
        #pragma unroll
        for (int off = 4; off; off >>= 1)
            v = fmaxf(v, __shfl_xor_sync(0xffu, v, off));
        if (threadIdx.x == 0) rbuf[0] = v;
    }
    __syncthreads();
    float r = rbuf[0];
    __syncthreads();
    return r;
}

__device__ __forceinline__ float blk_sum(float v, float* rbuf) {
    #pragma unroll
    for (int off = 16; off; off >>= 1)
        v += __shfl_xor_sync(0xffffffffu, v, off);
    if ((threadIdx.x & 31) == 0) rbuf[threadIdx.x >> 5] = v;
    __syncthreads();
    if (threadIdx.x < 8) {
        v = rbuf[threadIdx.x];
        #pragma unroll
        for (int off = 4; off; off >>= 1)
            v += __shfl_xor_sync(0xffu, v, off);
        if (threadIdx.x == 0) rbuf[0] = v;
    }
    __syncthreads();
    float r = rbuf[0];
    __syncthreads();
    return r;
}

__device__ __forceinline__ unsigned f2key(float f) {
    unsigned u = __float_as_uint(f);
    return (u & 0x80000000u) ? ~u : (u | 0x80000000u);
}

// ---------------------------------------------------------------------------
__global__ void __launch_bounds__(256) cggr_kernel(
    const float* __restrict__ lf, const int* __restrict__ tf,
    const int* __restrict__ step_ptr, float* __restrict__ out,
    int V, int N, float inv_logV)
{
    const int row  = blockIdx.x;
    const int tid  = threadIdx.x;
    const int lane = tid & 31;
    const float* p = lf + (size_t)row * (size_t)V;

    __shared__ __align__(128) float4 pipe[NST][TILE_F4];   // 36 KB ring
    __shared__ __align__(8) unsigned long long mbar[2 * NST]; // full[0..2], empty[3..5]
    __shared__ float rbuf[8];
    __shared__ OS swarp[8];
    __shared__ unsigned hist[256];
    __shared__ unsigned suf[257];
    __shared__ unsigned s_prefix;
    __shared__ int s_rank;
    __shared__ int s_last;
    __shared__ float s_lt;

    const uint32_t mb0 = smem_u32(&mbar[0]);
    #define FULL_BAR(s)  (mb0 + (uint32_t)(s) * 8u)
    #define EMPTY_BAR(s) (mb0 + (uint32_t)(NST + (s)) * 8u)

    // prefetch target logit before the stream evicts the line
    if (tid == 0) s_lt = __ldg(p + __ldg(tf + row));

    // ---- phase 1: per-row streaming stats ----
    float m1 = -INFINITY, m2 = -INFINITY;
    float bm = -INFINITY, b2 = -INFINITY;
    float s0 = 0.f, s1 = 0.f, t0 = 0.f, t1 = 0.f;

    #define TOP2(x) { float lo_ = fminf((x), m1); m1 = fmaxf((x), m1); m2 = fmaxf(m2, lo_); }
    #define RESCALE() if (m1 > bm) { \
        float nb2_ = m1 * LOG2E; \
        float sc_  = ex2f(b2 - nb2_); \
        s0 *= sc_; s1 *= sc_; t0 *= sc_; t1 *= sc_; \
        bm = m1; b2 = nb2_; }
    #define EXP4(v) { float e_; \
        e_ = ex2f(fmaf((v).x, LOG2E, -b2)); s0 += e_; t0 = fmaf(e_, (v).x, t0); \
        e_ = ex2f(fmaf((v).y, LOG2E, -b2)); s1 += e_; t1 = fmaf(e_, (v).y, t1); \
        e_ = ex2f(fmaf((v).z, LOG2E, -b2)); s0 += e_; t0 = fmaf(e_, (v).z, t0); \
        e_ = ex2f(fmaf((v).w, LOG2E, -b2)); s1 += e_; t1 = fmaf(e_, (v).w, t1); }

    if ((V & 3) == 0) {
        const uint32_t nbytes = (uint32_t)V * 4u;
        const int tiles = (int)((nbytes + TILE_BYTES - 1) / TILE_BYTES);

        if (tid == 0) {
            #pragma unroll
            for (int s = 0; s < NST; s++) {
                MBAR_INIT(FULL_BAR(s), 1);
                MBAR_INIT(EMPTY_BAR(s), 256);
            }
        }
        __syncthreads();

        // prologue: issue up to NST tiles
        if (tid == 0) {
            #pragma unroll
            for (int s = 0; s < NST; s++) {
                if (s < tiles) {
                    uint32_t off = (uint32_t)s * TILE_BYTES;
                    uint32_t tb  = min((uint32_t)TILE_BYTES, nbytes - off);
                    MBAR_EXPECT_TX(FULL_BAR(s), tb);
                    bulk_g2s(smem_u32(&pipe[s][0]), (const char*)p + off, tb, FULL_BAR(s));
                }
            }
        }

        int stage = 0;
        uint32_t pf = 0;
        #pragma unroll 1
        for (int t = 0; t < tiles; t++) {
            mbar_wait(FULL_BAR(stage), pf);   // acquire: tile data visible

            uint32_t off = (uint32_t)t * TILE_BYTES;
            uint32_t tb  = min((uint32_t)TILE_BYTES, nbytes - off);
            if (tb == TILE_BYTES) {
                // full tile: exactly 3 float4 per thread
                float4 a = pipe[stage][tid];
                float4 b = pipe[stage][tid + 256];
                float4 c = pipe[stage][tid + 512];
                TOP2(a.x); TOP2(a.y); TOP2(a.z); TOP2(a.w);
                TOP2(b.x); TOP2(b.y); TOP2(b.z); TOP2(b.w);
                TOP2(c.x); TOP2(c.y); TOP2(c.z); TOP2(c.w);
                RESCALE();
                EXP4(a);
                EXP4(b);
                EXP4(c);
            } else {
                int nf4 = (int)(tb >> 4);
                for (int j = tid; j < nf4; j += 256) {
                    float4 a = pipe[stage][j];
                    TOP2(a.x); TOP2(a.y); TOP2(a.z); TOP2(a.w);
                    RESCALE();
                    EXP4(a);
                }
            }

            MBAR_ARRIVE(EMPTY_BAR(stage));

            if (tid == 0 && t + NST < tiles) {
                mbar_wait_relaxed(EMPTY_BAR(stage), pf);   // stage drained
                uint32_t noff = (uint32_t)(t + NST) * TILE_BYTES;
                uint32_t ntb  = min((uint32_t)TILE_BYTES, nbytes - noff);
                MBAR_EXPECT_TX(FULL_BAR(stage), ntb);
                bulk_g2s(smem_u32(&pipe[stage][0]), (const char*)p + noff, ntb, FULL_BAR(stage));
            }

            if (++stage == NST) { stage = 0; pf ^= 1u; }
        }
    } else {
        for (int i = tid; i < V; i += 256) {
            float x = p[i];
            TOP2(x);
            RESCALE();
            float e = ex2f(fmaf(x, LOG2E, -b2));
            s0 += e; t0 = fmaf(e, x, t0);
        }
        __syncthreads();
    }
    #undef TOP2
    #undef RESCALE
    #undef EXP4

    OS st;
    st.m1 = m1; st.m2 = m2; st.s = s0 + s1; st.t = t0 + t1;

    #pragma unroll
    for (int off = 16; off; off >>= 1) {
        OS o;
        o.m1 = __shfl_xor_sync(0xffffffffu, st.m1, off);
        o.m2 = __shfl_xor_sync(0xffffffffu, st.m2, off);
        o.s  = __shfl_xor_sync(0xffffffffu, st.s,  off);
        o.t  = __shfl_xor_sync(0xffffffffu, st.t,  off);
        os_merge(st, o);
    }
    if (lane == 0) swarp[tid >> 5] = st;
    __syncthreads();

    if (tid == 0) {
        #pragma unroll
        for (int w = 1; w < 8; w++) os_merge(st, swarp[w]);

        float logs = __logf(st.s);
        float logZ = st.m1 + logs;
        float ce   = logZ - s_lt;
        float ent  = logZ - st.t / st.s;
        float conf = 1.f / st.s;                    // p1
        float p2   = __expf(st.m2 - st.m1) * conf;  // p2
        float margin = conf - p2;

        g_ce[row]   = ce;
        g_conf[row] = conf;
        g_part[row] = ent * inv_logV + 1.f - margin;

        __threadfence();
        unsigned prev = atomicAdd(&g_done, 1u);
        s_last = (prev == (unsigned)(N - 1)) ? 1 : 0;
    }
    __syncthreads();
    if (!s_last) return;

    // ---- phase 2: finalize (single surviving block) ----
    __threadfence();

    float mce = -INFINITY, sconf = 0.f;
    for (int i = tid; i < N; i += 256) {
        mce = fmaxf(mce, __ldcg(&g_ce[i]));
        sconf += __ldcg(&g_conf[i]);
    }
    float maxce   = blk_max(mce, rbuf);
    float sumconf = blk_sum(sconf, rbuf);

    float invm = 1.f / (maxce + 1e-6f);
    for (int i = tid; i < N; i += 256) {
        float d = (__ldcg(&g_part[i]) + __ldcg(&g_ce[i]) * invm) * (1.f / 3.f);
        g_key[i] = f2key(d);
    }

    if (tid == 0) {
        int   step     = *step_ptr;
        float progress = fminf(1.f, (float)step * (1.f / 1000.f));
        float base_rat = 1.f - progress * (1.f - 0.25f);
        float avg_conf = sumconf / (float)N;
        float ratio    = base_rat * (1.f + 0.5f * (0.5f - avg_conf) * 2.f);
        ratio = fminf(fmaxf(ratio, 0.01f), 1.f);
        int k = (int)rintf(ratio * (float)N);       // round-half-even == jnp.round
        k = min(max(k, 1), N);
        s_rank = k;
        s_prefix = 0u;
    }
    __syncthreads();

    const int Npad = (N + 255) & ~255;

    #pragma unroll
    for (int pass = 0; pass < 4; pass++) {
        const int shift = 24 - pass * 8;
        const unsigned himask = (pass == 0) ? 0u : (0xFFFFFFFFu << (32 - pass * 8));
        hist[tid] = 0u;
        __syncthreads();
        unsigned prefix = s_prefix;

        for (int i = tid; i < Npad; i += 256) {
            int digit = -1;
            if (i < N) {
                unsigned key = g_key[i];
                if ((key & himask) == prefix) digit = (int)((key >> shift) & 255u);
            }
            unsigned m = __match_any_sync(0xffffffffu, digit);
            int leader = __ffs(m) - 1;
            if (lane == leader && digit >= 0)
                atomicAdd(&hist[digit], (unsigned)__popc(m));
        }
        __syncthreads();

        suf[tid] = hist[tid];
        __syncthreads();
        #pragma unroll
        for (int off = 1; off < 256; off <<= 1) {
            unsigned add = (tid + off < 256) ? suf[tid + off] : 0u;
            __syncthreads();
            suf[tid] += add;
            __syncthreads();
        }

        int r = s_rank;
        unsigned here  = suf[tid];
        unsigned above = (tid == 255) ? 0u : suf[tid + 1];
        if ((int)here >= r && (int)above < r) {
            s_prefix = prefix | ((unsigned)tid << shift);
            s_rank = r - (int)above;
        }
        __syncthreads();
    }
    unsigned thr_key = s_prefix;   // exact k-th largest difficulty key

    float sce = 0.f, cnt = 0.f;
    for (int i = tid; i < N; i += 256) {
        if (g_key[i] >= thr_key) { sce += __ldcg(&g_ce[i]); cnt += 1.f; }
    }
    sce = blk_sum(sce, rbuf);
    cnt = blk_sum(cnt, rbuf);
    if (tid == 0) {
        out[0] = sce / fmaxf(cnt, 1.f);
        g_done = 0;               // reset for next graph replay
    }
}

// ---------------------------------------------------------------------------
extern "C" void kernel_launch(void* const* d_in, const int* in_sizes, int n_in,
                              void* d_out, int out_size) {
    const float* lf   = (const float*)d_in[0];   // logits (B,S,V) fp32
    const int*   tf   = (const int*)d_in[1];     // targets (B,S) int32
    const int*   step = (const int*)d_in[2];     // step_count scalar int32

    int N = in_sizes[1];                 // B*S = 8192
    int V = in_sizes[0] / N;             // 32000
    if (N > MAXN) N = MAXN;

    float inv_logV = 1.f / logf((float)V);

    cggr_kernel<<<N, 256>>>(lf, tf, step, (float*)d_out, V, N, inv_logV);
}

// round 10
// speedup vs baseline: 1.3240x; 1.3240x over previous
#include <cuda_runtime.h>
#include <math.h>
#include <stdint.h>

// CGGRLoss fused, R10: warp-specialized bulk-async pipeline.
// 288 threads/block: 256 consumers + producer warp (thread 256 issues
// cp.async.bulk refills the moment a stage drains). 5-stage x 8KB smem ring,
// mbarrier full/empty pairs. Last block finalizes (reductions, exact k-th
// largest radix select, masked-mean CE).

#define MAXN 8192
#define LOG2E 1.4426950408889634f
#define NST 5
#define TILE_BYTES 8192           // 512 float4 = 2 per consumer thread
#define TILE_F4 (TILE_BYTES / 16)
#define NTHR 288
#define NCONS 256

static __device__ float g_ce[MAXN];
static __device__ float g_conf[MAXN];
static __device__ float g_part[MAXN];     // ent_norm + 1 - margin
static __device__ unsigned g_key[MAXN];   // finalize scratch (radix keys)
static __device__ unsigned g_done;        // zero-init; reset in-kernel

__device__ __forceinline__ float ex2f(float x) {
    float y;
    asm("ex2.approx.ftz.f32 %0, %1;" : "=f"(y) : "f"(x));
    return y;   // ex2(-inf) = +0, ex2(0) = 1 exactly
}

__device__ __forceinline__ uint32_t smem_u32(const void* ptr) {
    uint32_t a;
    asm("{ .reg .u64 t; cvta.to.shared.u64 t, %1; cvt.u32.u64 %0, t; }"
        : "=r"(a) : "l"(ptr));
    return a;
}

#define MBAR_INIT(a, c) \
    asm volatile("mbarrier.init.shared.b64 [%0], %1;" :: "r"(a), "r"(c) : "memory")
#define MBAR_EXPECT_TX(a, b) \
    asm volatile("mbarrier.arrive.expect_tx.shared.b64 _, [%0], %1;" :: "r"(a), "r"(b) : "memory")
#define MBAR_ARRIVE(a) \
    asm volatile("mbarrier.arrive.shared.b64 _, [%0];" :: "r"(a) : "memory")

__device__ __forceinline__ void mbar_wait(uint32_t mbar, uint32_t parity) {
    asm volatile(
        "{\n\t"
        ".reg .pred P;\n\t"
        "WL_%=:\n\t"
        "mbarrier.try_wait.parity.acquire.cta.shared::cta.b64 P, [%0], %1, 0x989680;\n\t"
        "@P bra.uni WD_%=;\n\t"
        "bra.uni WL_%=;\n\t"
        "WD_%=:\n\t"
        "}"
        :: "r"(mbar), "r"(parity) : "memory");
}

__device__ __forceinline__ void mbar_wait_relaxed(uint32_t mbar, uint32_t parity) {
    asm volatile(
        "{\n\t"
        ".reg .pred P;\n\t"
        "WL_%=:\n\t"
        "mbarrier.try_wait.parity.relaxed.cta.shared::cta.b64 P, [%0], %1, 0x989680;\n\t"
        "@P bra.uni WD_%=;\n\t"
        "bra.uni WL_%=;\n\t"
        "WD_%=:\n\t"
        "}"
        :: "r"(mbar), "r"(parity) : "memory");
}

__device__ __forceinline__ void bulk_g2s(uint32_t dst_smem, const void* src_gmem,
                                         uint32_t bytes, uint32_t mbar) {
    asm volatile(
        "cp.async.bulk.shared::cta.global.mbarrier::complete_tx::bytes "
        "[%0], [%1], %2, [%3];"
        :: "r"(dst_smem), "l"(src_gmem), "r"(bytes), "r"(mbar) : "memory");
}

struct OS { float m1, m2, s, t; };

__device__ __forceinline__ void os_merge(OS& a, const OS& b) {
    float M1 = fmaxf(a.m1, b.m1);
    float M2 = fmaxf(fminf(a.m1, b.m1), fmaxf(a.m2, b.m2));
    float sa = (a.m1 == -INFINITY) ? 0.f : __expf(a.m1 - M1);
    float sb = (b.m1 == -INFINITY) ? 0.f : __expf(b.m1 - M1);
    a.s = a.s * sa + b.s * sb;
    a.t = a.t * sa + b.t * sb;
    a.m1 = M1; a.m2 = M2;
}

// block reductions for 9 warps (288 threads)
__device__ __forceinline__ float blk_max(float v, float* rbuf) {
    #pragma unroll
    for (int off = 16; off; off >>= 1)
        v = fmaxf(v, __shfl_xor_sync(0xffffffffu, v, off));
    if ((threadIdx.x & 31) == 0) rbuf[threadIdx.x >> 5] = v;
    __syncthreads();
    if (threadIdx.x < 32) {
        v = (threadIdx.x < 9) ? rbuf[threadIdx.x] : -INFINITY;
        #pragma unroll
        for (int off = 16; off; off >>= 1)
            v = fmaxf(v, __shfl_xor_sync(0xffffffffu, v, off));
        if (threadIdx.x == 0) rbuf[0] = v;
    }
    __syncthreads();
    float r = rbuf[0];
    __syncthreads();
    return r;
}

__device__ __forceinline__ float blk_sum(float v, float* rbuf) {
    #pragma unroll
    for (int off = 16; off; off >>= 1)
        v += __shfl_xor_sync(0xffffffffu, v, off);
    if ((threadIdx.x & 31) == 0) rbuf[threadIdx.x >> 5] = v;
    __syncthreads();
    if (threadIdx.x < 32) {
        v = (threadIdx.x < 9) ? rbuf[threadIdx.x] : 0.f;
        #pragma unroll
        for (int off = 16; off; off >>= 1)
            v += __shfl_xor_sync(0xffffffffu, v, off);
        if (threadIdx.x == 0) rbuf[0] = v;
    }
    __syncthreads();
    float r = rbuf[0];
    __syncthreads();
    return r;
}

__device__ __forceinline__ unsigned f2key(float f) {
    unsigned u = __float_as_uint(f);
    return (u & 0x80000000u) ? ~u : (u | 0x80000000u);
}

// ---------------------------------------------------------------------------
__global__ void __launch_bounds__(NTHR) cggr_kernel(
    const float* __restrict__ lf, const int* __restrict__ tf,
    const int* __restrict__ step_ptr, float* __restrict__ out,
    int V, int N, float inv_logV)
{
    const int row  = blockIdx.x;
    const int tid  = threadIdx.x;
    const int lane = tid & 31;
    const float* p = lf + (size_t)row * (size_t)V;

    __shared__ __align__(128) float4 pipe[NST][TILE_F4];      // 40 KB ring
    __shared__ __align__(8) unsigned long long mbar[2 * NST]; // full / empty
    __shared__ float rbuf[16];
    __shared__ OS swarp[9];
    __shared__ unsigned hist[256];
    __shared__ unsigned suf[257];
    __shared__ unsigned s_prefix;
    __shared__ int s_rank;
    __shared__ int s_last;
    __shared__ float s_lt;

    const uint32_t mb0 = smem_u32(&mbar[0]);
    #define FULL_BAR(s)  (mb0 + (uint32_t)(s) * 8u)
    #define EMPTY_BAR(s) (mb0 + (uint32_t)(NST + (s)) * 8u)

    // prefetch target logit before the stream evicts the line
    if (tid == 0) s_lt = __ldg(p + __ldg(tf + row));

    // ---- phase 1: per-row streaming stats ----
    float m1 = -INFINITY, m2 = -INFINITY;
    float bm = -INFINITY, b2 = -INFINITY;
    float s0 = 0.f, s1 = 0.f, t0 = 0.f, t1 = 0.f;

    #define TOP2(x) { float lo_ = fminf((x), m1); m1 = fmaxf((x), m1); m2 = fmaxf(m2, lo_); }
    #define RESCALE() if (m1 > bm) { \
        float nb2_ = m1 * LOG2E; \
        float sc_  = ex2f(b2 - nb2_); \
        s0 *= sc_; s1 *= sc_; t0 *= sc_; t1 *= sc_; \
        bm = m1; b2 = nb2_; }
    #define EXP4(v) { float e_; \
        e_ = ex2f(fmaf((v).x, LOG2E, -b2)); s0 += e_; t0 = fmaf(e_, (v).x, t0); \
        e_ = ex2f(fmaf((v).y, LOG2E, -b2)); s1 += e_; t1 = fmaf(e_, (v).y, t1); \
        e_ = ex2f(fmaf((v).z, LOG2E, -b2)); s0 += e_; t0 = fmaf(e_, (v).z, t0); \
        e_ = ex2f(fmaf((v).w, LOG2E, -b2)); s1 += e_; t1 = fmaf(e_, (v).w, t1); }

    if ((V & 3) == 0) {
        const uint32_t nbytes = (uint32_t)V * 4u;
        const int tiles = (int)((nbytes + TILE_BYTES - 1) / TILE_BYTES);

        if (tid == 0) {
            #pragma unroll
            for (int s = 0; s < NST; s++) {
                MBAR_INIT(FULL_BAR(s), 1);
                MBAR_INIT(EMPTY_BAR(s), NCONS);
            }
        }
        __syncthreads();

        if (tid == NCONS) {
            // ---- dedicated producer thread ----
            #pragma unroll 1
            for (int t = 0; t < tiles; t++) {
                int s = t % NST;
                int r = t / NST;
                if (t >= NST)
                    mbar_wait_relaxed(EMPTY_BAR(s), (unsigned)((r - 1) & 1));
                uint32_t off = (uint32_t)t * TILE_BYTES;
                uint32_t tb  = min((uint32_t)TILE_BYTES, nbytes - off);
                MBAR_EXPECT_TX(FULL_BAR(s), tb);
                bulk_g2s(smem_u32(&pipe[s][0]), (const char*)p + off, tb, FULL_BAR(s));
            }
        } else if (tid < NCONS) {
            // ---- 256 consumers ----
            int stage = 0;
            uint32_t pf = 0;
            #pragma unroll 1
            for (int t = 0; t < tiles; t++) {
                mbar_wait(FULL_BAR(stage), pf);   // acquire

                uint32_t off = (uint32_t)t * TILE_BYTES;
                uint32_t tb  = min((uint32_t)TILE_BYTES, nbytes - off);
                if (tb == TILE_BYTES) {
                    float4 a = pipe[stage][tid];
                    float4 b = pipe[stage][tid + 256];
                    TOP2(a.x); TOP2(a.y); TOP2(a.z); TOP2(a.w);
                    TOP2(b.x); TOP2(b.y); TOP2(b.z); TOP2(b.w);
                    RESCALE();
                    EXP4(a);
                    EXP4(b);
                } else {
                    int nf4 = (int)(tb >> 4);
                    for (int j = tid; j < nf4; j += NCONS) {
                        float4 a = pipe[stage][j];
                        TOP2(a.x); TOP2(a.y); TOP2(a.z); TOP2(a.w);
                        RESCALE();
                        EXP4(a);
                    }
                }
                MBAR_ARRIVE(EMPTY_BAR(stage));
                if (++stage == NST) { stage = 0; pf ^= 1u; }
            }
        }
        // producer-warp lanes 1..31 fall through immediately (identity state)
    } else {
        for (int i = tid; i < V; i += NTHR) {
            float x = p[i];
            TOP2(x);
            RESCALE();
            float e = ex2f(fmaf(x, LOG2E, -b2));
            s0 += e; t0 = fmaf(e, x, t0);
        }
    }
    #undef TOP2
    #undef RESCALE
    #undef EXP4

    OS st;
    st.m1 = m1; st.m2 = m2; st.s = s0 + s1; st.t = t0 + t1;

    #pragma unroll
    for (int off = 16; off; off >>= 1) {
        OS o;
        o.m1 = __shfl_xor_sync(0xffffffffu, st.m1, off);
        o.m2 = __shfl_xor_sync(0xffffffffu, st.m2, off);
        o.s  = __shfl_xor_sync(0xffffffffu, st.s,  off);
        o.t  = __shfl_xor_sync(0xffffffffu, st.t,  off);
        os_merge(st, o);
    }
    if (lane == 0) swarp[tid >> 5] = st;
    __syncthreads();

    if (tid == 0) {
        #pragma unroll
        for (int w = 1; w < 9; w++) os_merge(st, swarp[w]);

        float logs = __logf(st.s);
        float logZ = st.m1 + logs;
        float ce   = logZ - s_lt;
        float ent  = logZ - st.t / st.s;
        float conf = 1.f / st.s;                    // p1
        float p2   = __expf(st.m2 - st.m1) * conf;  // p2
        float margin = conf - p2;

        g_ce[row]   = ce;
        g_conf[row] = conf;
        g_part[row] = ent * inv_logV + 1.f - margin;

        __threadfence();
        unsigned prev = atomicAdd(&g_done, 1u);
        s_last = (prev == (unsigned)(N - 1)) ? 1 : 0;
    }
    __syncthreads();
    if (!s_last) return;

    // ---- phase 2: finalize (single surviving block, 288 threads) ----
    __threadfence();

    float mce = -INFINITY, sconf = 0.f;
    for (int i = tid; i < N; i += NTHR) {
        mce = fmaxf(mce, __ldcg(&g_ce[i]));
        sconf += __ldcg(&g_conf[i]);
    }
    float maxce   = blk_max(mce, rbuf);
    float sumconf = blk_sum(sconf, rbuf);

    float invm = 1.f / (maxce + 1e-6f);
    for (int i = tid; i < N; i += NTHR) {
        float d = (__ldcg(&g_part[i]) + __ldcg(&g_ce[i]) * invm) * (1.f / 3.f);
        g_key[i] = f2key(d);
    }

    if (tid == 0) {
        int   step     = *step_ptr;
        float progress = fminf(1.f, (float)step * (1.f / 1000.f));
        float base_rat = 1.f - progress * (1.f - 0.25f);
        float avg_conf = sumconf / (float)N;
        float ratio    = base_rat * (1.f + 0.5f * (0.5f - avg_conf) * 2.f);
        ratio = fminf(fmaxf(ratio, 0.01f), 1.f);
        int k = (int)rintf(ratio * (float)N);       // round-half-even == jnp.round
        k = min(max(k, 1), N);
        s_rank = k;
        s_prefix = 0u;
    }
    __syncthreads();

    const int Npad = ((N + NTHR - 1) / NTHR) * NTHR;

    #pragma unroll
    for (int pass = 0; pass < 4; pass++) {
        const int shift = 24 - pass * 8;
        const unsigned himask = (pass == 0) ? 0u : (0xFFFFFFFFu << (32 - pass * 8));
        if (tid < 256) hist[tid] = 0u;
        __syncthreads();
        unsigned prefix = s_prefix;

        for (int i = tid; i < Npad; i += NTHR) {
            int digit = -1;
            if (i < N) {
                unsigned key = g_key[i];
                if ((key & himask) == prefix) digit = (int)((key >> shift) & 255u);
            }
            unsigned m = __match_any_sync(0xffffffffu, digit);
            int leader = __ffs(m) - 1;
            if (lane == leader && digit >= 0)
                atomicAdd(&hist[digit], (unsigned)__popc(m));
        }
        __syncthreads();

        if (tid < 256) suf[tid] = hist[tid];
        __syncthreads();
        #pragma unroll
        for (int off = 1; off < 256; off <<= 1) {
            unsigned add = (tid < 256 && tid + off < 256) ? suf[tid + off] : 0u;
            __syncthreads();
            if (tid < 256) suf[tid] += add;
            __syncthreads();
        }

        int r = s_rank;
        if (tid < 256) {
            unsigned here  = suf[tid];
            unsigned above = (tid == 255) ? 0u : suf[tid + 1];
            if ((int)here >= r && (int)above < r) {
                s_prefix = prefix | ((unsigned)tid << shift);
                s_rank = r - (int)above;
            }
        }
        __syncthreads();
    }
    unsigned thr_key = s_prefix;   // exact k-th largest difficulty key

    float sce = 0.f, cnt = 0.f;
    for (int i = tid; i < N; i += NTHR) {
        if (g_key[i] >= thr_key) { sce += __ldcg(&g_ce[i]); cnt += 1.f; }
    }
    sce = blk_sum(sce, rbuf);
    cnt = blk_sum(cnt, rbuf);
    if (tid == 0) {
        out[0] = sce / fmaxf(cnt, 1.f);
        g_done = 0;               // reset for next graph replay
    }
}

// ---------------------------------------------------------------------------
extern "C" void kernel_launch(void* const* d_in, const int* in_sizes, int n_in,
                              void* d_out, int out_size) {
    const float* lf   = (const float*)d_in[0];   // logits (B,S,V) fp32
    const int*   tf   = (const int*)d_in[1];     // targets (B,S) int32
    const int*   step = (const int*)d_in[2];     // step_count scalar int32

    int N = in_sizes[1];                 // B*S = 8192
    int V = in_sizes[0] / N;             // 32000
    if (N > MAXN) N = MAXN;

    float inv_logV = 1.f / logf((float)V);

    cggr_kernel<<<N, NTHR>>>(lf, tf, step, (float*)d_out, V, N, inv_logV);
}

// round 11
// speedup vs baseline: 1.4253x; 1.0765x over previous
#include <cuda_runtime.h>
#include <math.h>
#include <stdint.h>

// CGGRLoss fused, R11: dual-path streaming. Even 8KB chunks of each row come
// through the LDG/MSHR path (R5's pair loop), odd 8KB chunks through the
// cp.async.bulk copy-engine path into a 3-stage smem ring. The two request
// pools are independent, so their bandwidths add. Math identical to R5.

#define MAXN 8192
#define LOG2E 1.4426950408889634f
#define NST 3
#define CHUNK_BYTES 8192
#define CHUNK_F4 512               // float4 per chunk (2 per thread)

static __device__ float g_ce[MAXN];
static __device__ float g_conf[MAXN];
static __device__ float g_part[MAXN];     // ent_norm + 1 - margin
static __device__ unsigned g_key[MAXN];   // finalize scratch (radix keys)
static __device__ unsigned g_done;        // zero-init; reset in-kernel

__device__ __forceinline__ float ex2f(float x) {
    float y;
    asm("ex2.approx.ftz.f32 %0, %1;" : "=f"(y) : "f"(x));
    return y;   // ex2(-inf) = +0, ex2(0) = 1 exactly
}

__device__ __forceinline__ uint32_t smem_u32(const void* ptr) {
    uint32_t a;
    asm("{ .reg .u64 t; cvta.to.shared.u64 t, %1; cvt.u32.u64 %0, t; }"
        : "=r"(a) : "l"(ptr));
    return a;
}

#define MBAR_INIT(a, c) \
    asm volatile("mbarrier.init.shared.b64 [%0], %1;" :: "r"(a), "r"(c) : "memory")
#define MBAR_EXPECT_TX(a, b) \
    asm volatile("mbarrier.arrive.expect_tx.shared.b64 _, [%0], %1;" :: "r"(a), "r"(b) : "memory")
#define MBAR_ARRIVE(a) \
    asm volatile("mbarrier.arrive.shared.b64 _, [%0];" :: "r"(a) : "memory")

__device__ __forceinline__ void mbar_wait(uint32_t mbar, uint32_t parity) {
    asm volatile(
        "{\n\t"
        ".reg .pred P;\n\t"
        "WL_%=:\n\t"
        "mbarrier.try_wait.parity.acquire.cta.shared::cta.b64 P, [%0], %1, 0x989680;\n\t"
        "@P bra.uni WD_%=;\n\t"
        "bra.uni WL_%=;\n\t"
        "WD_%=:\n\t"
        "}"
        :: "r"(mbar), "r"(parity) : "memory");
}

__device__ __forceinline__ void mbar_wait_relaxed(uint32_t mbar, uint32_t parity) {
    asm volatile(
        "{\n\t"
        ".reg .pred P;\n\t"
        "WL_%=:\n\t"
        "mbarrier.try_wait.parity.relaxed.cta.shared::cta.b64 P, [%0], %1, 0x989680;\n\t"
        "@P bra.uni WD_%=;\n\t"
        "bra.uni WL_%=;\n\t"
        "WD_%=:\n\t"
        "}"
        :: "r"(mbar), "r"(parity) : "memory");
}

__device__ __forceinline__ void bulk_g2s(uint32_t dst_smem, const void* src_gmem,
                                         uint32_t bytes, uint32_t mbar) {
    asm volatile(
        "cp.async.bulk.shared::cta.global.mbarrier::complete_tx::bytes "
        "[%0], [%1], %2, [%3];"
        :: "r"(dst_smem), "l"(src_gmem), "r"(bytes), "r"(mbar) : "memory");
}

struct OS { float m1, m2, s, t; };

__device__ __forceinline__ void os_merge(OS& a, const OS& b) {
    float M1 = fmaxf(a.m1, b.m1);
    float M2 = fmaxf(fminf(a.m1, b.m1), fmaxf(a.m2, b.m2));
    float sa = (a.m1 == -INFINITY) ? 0.f : __expf(a.m1 - M1);
    float sb = (b.m1 == -INFINITY) ? 0.f : __expf(b.m1 - M1);
    a.s = a.s * sa + b.s * sb;
    a.t = a.t * sa + b.t * sb;
    a.m1 = M1; a.m2 = M2;
}

__device__ __forceinline__ float blk_max(float v, float* rbuf) {
    #pragma unroll
    for (int off = 16; off; off >>= 1)
        v = fmaxf(v, __shfl_xor_sync(0xffffffffu, v, off));
    if ((threadIdx.x & 31) == 0) rbuf[threadIdx.x >> 5] = v;
    __syncthreads();
    if (threadIdx.x < 8) {
        v = rbuf[threadIdx.x];
        #pragma unroll
        for (int off = 4; off; off >>= 1)
            v = fmaxf(v, __shfl_xor_sync(0xffu, v, off));
        if (threadIdx.x == 0) rbuf[0] = v;
    }
    __syncthreads();
    float r = rbuf[0];
    __syncthreads();
    return r;
}

__device__ __forceinline__ float blk_sum(float v, float* rbuf) {
    #pragma unroll
    for (int off = 16; off; off >>= 1)
        v += __shfl_xor_sync(0xffffffffu, v, off);
    if ((threadIdx.x & 31) == 0) rbuf[threadIdx.x >> 5] = v;
    __syncthreads();
    if (threadIdx.x < 8) {
        v = rbuf[threadIdx.x];
        #pragma unroll
        for (int off = 4; off; off >>= 1)
            v += __shfl_xor_sync(0xffu, v, off);
        if (threadIdx.x == 0) rbuf[0] = v;
    }
    __syncthreads();
    float r = rbuf[0];
    __syncthreads();
    return r;
}

__device__ __forceinline__ unsigned f2key(float f) {
    unsigned u = __float_as_uint(f);
    return (u & 0x80000000u) ? ~u : (u | 0x80000000u);
}

// ---------------------------------------------------------------------------
__global__ void __launch_bounds__(256) cggr_kernel(
    const float* __restrict__ lf, const int* __restrict__ tf,
    const int* __restrict__ step_ptr, float* __restrict__ out,
    int V, int N, float inv_logV)
{
    const int row  = blockIdx.x;
    const int tid  = threadIdx.x;
    const int lane = tid & 31;
    const float* p = lf + (size_t)row * (size_t)V;

    __shared__ __align__(128) float4 pipe[NST][CHUNK_F4];     // 24 KB ring
    __shared__ __align__(8) unsigned long long mbar[2 * NST]; // full / empty
    __shared__ float rbuf[8];
    __shared__ OS swarp[8];
    __shared__ unsigned hist[256];
    __shared__ unsigned suf[257];
    __shared__ unsigned s_prefix;
    __shared__ int s_rank;
    __shared__ int s_last;
    __shared__ float s_lt;

    const uint32_t mb0 = smem_u32(&mbar[0]);
    #define FULL_BAR(s)  (mb0 + (uint32_t)(s) * 8u)
    #define EMPTY_BAR(s) (mb0 + (uint32_t)(NST + (s)) * 8u)

    // prefetch target logit before the stream evicts the line
    if (tid == 0) s_lt = __ldg(p + __ldg(tf + row));

    // ---- phase 1: per-row streaming stats ----
    float m1 = -INFINITY, m2 = -INFINITY;
    float bm = -INFINITY, b2 = -INFINITY;
    float s0 = 0.f, s1 = 0.f, t0 = 0.f, t1 = 0.f;

    #define TOP2(x) { float lo_ = fminf((x), m1); m1 = fmaxf((x), m1); m2 = fmaxf(m2, lo_); }
    #define RESCALE() if (m1 > bm) { \
        float nb2_ = m1 * LOG2E; \
        float sc_  = ex2f(b2 - nb2_); \
        s0 *= sc_; s1 *= sc_; t0 *= sc_; t1 *= sc_; \
        bm = m1; b2 = nb2_; }
    #define EXP4(v) { float e_; \
        e_ = ex2f(fmaf((v).x, LOG2E, -b2)); s0 += e_; t0 = fmaf(e_, (v).x, t0); \
        e_ = ex2f(fmaf((v).y, LOG2E, -b2)); s1 += e_; t1 = fmaf(e_, (v).y, t1); \
        e_ = ex2f(fmaf((v).z, LOG2E, -b2)); s0 += e_; t0 = fmaf(e_, (v).z, t0); \
        e_ = ex2f(fmaf((v).w, LOG2E, -b2)); s1 += e_; t1 = fmaf(e_, (v).w, t1); }
    #define PROC2(a, b) { \
        TOP2((a).x); TOP2((a).y); TOP2((a).z); TOP2((a).w); \
        TOP2((b).x); TOP2((b).y); TOP2((b).z); TOP2((b).w); \
        RESCALE(); \
        EXP4(a); \
        EXP4(b); }

    if (((V & 3) == 0) && ((((uintptr_t)p) & 127u) == 0)) {
        const int V4    = V >> 2;
        const int nfull = V4 / CHUNK_F4;     // full 8KB chunks
        const int nodd  = nfull >> 1;        // odd-index chunks -> bulk path
        const float4* p4 = reinterpret_cast<const float4*>(p);

        if (tid == 0) {
            #pragma unroll
            for (int s = 0; s < NST; s++) {
                MBAR_INIT(FULL_BAR(s), 1);
                MBAR_INIT(EMPTY_BAR(s), 256);
            }
        }
        __syncthreads();

        // prologue: issue first min(NST, nodd) odd chunks on the bulk path
        if (tid == 0) {
            #pragma unroll
            for (int s = 0; s < NST; s++) {
                if (s < nodd) {
                    MBAR_EXPECT_TX(FULL_BAR(s), CHUNK_BYTES);
                    bulk_g2s(smem_u32(&pipe[s][0]),
                             (const char*)p + (uint32_t)(2 * s + 1) * CHUNK_BYTES,
                             CHUNK_BYTES, FULL_BAR(s));
                }
            }
        }

        // prologue: first even chunk via LDG
        float4 g0, g1;
        if (nfull > 0) {
            g0 = __ldcs(p4 + tid);
            g1 = __ldcs(p4 + tid + 256);
        }

        #pragma unroll 1
        for (int j = 0; j < nodd; j++) {
            const int s = j % NST;
            const unsigned par = (unsigned)((j / NST) & 1);

            // prefetch next even chunk (2j+2) while bulk chunk lands
            float4 h0, h1;
            const int e2 = 2 * j + 2;
            const bool haveh = e2 < nfull;
            if (haveh) {
                h0 = __ldcs(p4 + e2 * CHUNK_F4 + tid);
                h1 = __ldcs(p4 + e2 * CHUNK_F4 + tid + 256);
            }

            // process current even chunk (register path)
            PROC2(g0, g1);

            // process odd chunk 2j+1 from the smem ring (bulk path)
            mbar_wait(FULL_BAR(s), par);
            float4 a = pipe[s][tid];
            float4 b = pipe[s][tid + 256];
            PROC2(a, b);
            MBAR_ARRIVE(EMPTY_BAR(s));

            // refill this stage with odd chunk j+NST
            if (tid == 0 && j + NST < nodd) {
                mbar_wait_relaxed(EMPTY_BAR(s), par);
                MBAR_EXPECT_TX(FULL_BAR(s), CHUNK_BYTES);
                bulk_g2s(smem_u32(&pipe[s][0]),
                         (const char*)p + (uint32_t)(2 * (j + NST) + 1) * CHUNK_BYTES,
                         CHUNK_BYTES, FULL_BAR(s));
            }

            g0 = h0; g1 = h1;
        }
        // leftover even chunk when nfull is odd (already in g0/g1)
        if (nfull & 1) { PROC2(g0, g1); }

        // tail: remaining float4s beyond full chunks
        for (int i = nfull * CHUNK_F4 + tid; i < V4; i += 256) {
            float4 a = __ldcs(p4 + i);
            TOP2(a.x); TOP2(a.y); TOP2(a.z); TOP2(a.w);
            RESCALE();
            EXP4(a);
        }
    } else {
        for (int i = tid; i < V; i += 256) {
            float x = p[i];
            TOP2(x);
            RESCALE();
            float e = ex2f(fmaf(x, LOG2E, -b2));
            s0 += e; t0 = fmaf(e, x, t0);
        }
    }
    #undef TOP2
    #undef RESCALE
    #undef EXP4
    #undef PROC2

    OS st;
    st.m1 = m1; st.m2 = m2; st.s = s0 + s1; st.t = t0 + t1;

    #pragma unroll
    for (int off = 16; off; off >>= 1) {
        OS o;
        o.m1 = __shfl_xor_sync(0xffffffffu, st.m1, off);
        o.m2 = __shfl_xor_sync(0xffffffffu, st.m2, off);
        o.s  = __shfl_xor_sync(0xffffffffu, st.s,  off);
        o.t  = __shfl_xor_sync(0xffffffffu, st.t,  off);
        os_merge(st, o);
    }
    if (lane == 0) swarp[tid >> 5] = st;
    __syncthreads();

    if (tid == 0) {
        #pragma unroll
        for (int w = 1; w < 8; w++) os_merge(st, swarp[w]);

        float logs = __logf(st.s);
        float logZ = st.m1 + logs;
        float ce   = logZ - s_lt;
        float ent  = logZ - st.t / st.s;
        float conf = 1.f / st.s;                    // p1
        float p2   = __expf(st.m2 - st.m1) * conf;  // p2
        float margin = conf - p2;

        g_ce[row]   = ce;
        g_conf[row] = conf;
        g_part[row] = ent * inv_logV + 1.f - margin;

        __threadfence();
        unsigned prev = atomicAdd(&g_done, 1u);
        s_last = (prev == (unsigned)(N - 1)) ? 1 : 0;
    }
    __syncthreads();
    if (!s_last) return;

    // ---- phase 2: finalize (single surviving block) ----
    __threadfence();

    float mce = -INFINITY, sconf = 0.f;
    for (int i = tid; i < N; i += 256) {
        mce = fmaxf(mce, __ldcg(&g_ce[i]));
        sconf += __ldcg(&g_conf[i]);
    }
    float maxce   = blk_max(mce, rbuf);
    float sumconf = blk_sum(sconf, rbuf);

    float invm = 1.f / (maxce + 1e-6f);
    for (int i = tid; i < N; i += 256) {
        float d = (__ldcg(&g_part[i]) + __ldcg(&g_ce[i]) * invm) * (1.f / 3.f);
        g_key[i] = f2key(d);
    }

    if (tid == 0) {
        int   step     = *step_ptr;
        float progress = fminf(1.f, (float)step * (1.f / 1000.f));
        float base_rat = 1.f - progress * (1.f - 0.25f);
        float avg_conf = sumconf / (float)N;
        float ratio    = base_rat * (1.f + 0.5f * (0.5f - avg_conf) * 2.f);
        ratio = fminf(fmaxf(ratio, 0.01f), 1.f);
        int k = (int)rintf(ratio * (float)N);       // round-half-even == jnp.round
        k = min(max(k, 1), N);
        s_rank = k;
        s_prefix = 0u;
    }
    __syncthreads();

    const int Npad = (N + 255) & ~255;

    #pragma unroll
    for (int pass = 0; pass < 4; pass++) {
        const int shift = 24 - pass * 8;
        const unsigned himask = (pass == 0) ? 0u : (0xFFFFFFFFu << (32 - pass * 8));
        hist[tid] = 0u;
        __syncthreads();
        unsigned prefix = s_prefix;

        for (int i = tid; i < Npad; i += 256) {
            int digit = -1;
            if (i < N) {
                unsigned key = g_key[i];
                if ((key & himask) == prefix) digit = (int)((key >> shift) & 255u);
            }
            unsigned m = __match_any_sync(0xffffffffu, digit);
            int leader = __ffs(m) - 1;
            if (lane == leader && digit >= 0)
                atomicAdd(&hist[digit], (unsigned)__popc(m));
        }
        __syncthreads();

        suf[tid] = hist[tid];
        __syncthreads();
        #pragma unroll
        for (int off = 1; off < 256; off <<= 1) {
            unsigned add = (tid + off < 256) ? suf[tid + off] : 0u;
            __syncthreads();
            suf[tid] += add;
            __syncthreads();
        }

        int r = s_rank;
        unsigned here  = suf[tid];
        unsigned above = (tid == 255) ? 0u : suf[tid + 1];
        if ((int)here >= r && (int)above < r) {
            s_prefix = prefix | ((unsigned)tid << shift);
            s_rank = r - (int)above;
        }
        __syncthreads();
    }
    unsigned thr_key = s_prefix;   // exact k-th largest difficulty key

    float sce = 0.f, cnt = 0.f;
    for (int i = tid; i < N; i += 256) {
        if (g_key[i] >= thr_key) { sce += __ldcg(&g_ce[i]); cnt += 1.f; }
    }
    sce = blk_sum(sce, rbuf);
    cnt = blk_sum(cnt, rbuf);
    if (tid == 0) {
        out[0] = sce / fmaxf(cnt, 1.f);
        g_done = 0;               // reset for next graph replay
    }
}

// ---------------------------------------------------------------------------
extern "C" void kernel_launch(void* const* d_in, const int* in_sizes, int n_in,
                              void* d_out, int out_size) {
    const float* lf   = (const float*)d_in[0];   // logits (B,S,V) fp32
    const int*   tf   = (const int*)d_in[1];     // targets (B,S) int32
    const int*   step = (const int*)d_in[2];     // step_count scalar int32

    int N = in_sizes[1];                 // B*S = 8192
    int V = in_sizes[0] / N;             // 32000
    if (N > MAXN) N = MAXN;

    float inv_logV = 1.f / logf((float)V);

    cggr_kernel<<<N, 256>>>(lf, tf, step, (float*)d_out, V, N, inv_logV);
}